// round 2
// baseline (speedup 1.0000x reference)
#include <cuda_runtime.h>
#include <cuda_bf16.h>

#define NVERT 4096
#define NBATCH 2
#define MAX_EDGES 49152   // hard bound: 6 ordered pairs * 8192 faces
#define ROW_CAP 1024      // per-row nonzero cap (true max degree ~ 40)

// -------- device scratch (no allocations allowed) --------
__device__ float        g_dxsub[NBATCH * NVERT * 3];
__device__ float        g_xsub [NBATCH * NVERT * 3];
__device__ float        g_acc  [NBATCH];
__device__ unsigned int g_num_edges;
__device__ unsigned int g_edges[MAX_EDGES];

// -------- kernel 0: reset accumulators (graph replays must be idempotent) ----
__global__ void init_kernel() {
    if (threadIdx.x == 0) {
        g_acc[0] = 0.f;
        g_acc[1] = 0.f;
        g_num_edges = 0u;
    }
}

// -------- kernel 1: fused dense matvec + edge-list collection ---------------
// One block per Laplacian row i. Streams the 16KB row once (float4, fully
// coalesced), accumulates the 12 matvec sums (dx/x x B x 3) for the nonzero
// columns, and records each nonzero (i,j) packed into 24 bits. Edge flush is
// shared-memory aggregated: ONE global atomicAdd per row.
__global__ __launch_bounds__(256) void matvec_collect_kernel(
    const float* __restrict__ L,
    const float* __restrict__ dx,
    const float* __restrict__ x)
{
    __shared__ unsigned int s_cnt;
    __shared__ unsigned int s_base;
    __shared__ unsigned int s_list[ROW_CAP];
    __shared__ float        s_red[8][12];

    if (threadIdx.x == 0) s_cnt = 0u;
    __syncthreads();

    const int i = blockIdx.x;
    const float4* Lrow = reinterpret_cast<const float4*>(L + (size_t)i * NVERT);

    const float* dx1 = dx + NVERT * 3;   // dx, batch 1 base
    const float* x1  = x  + NVERT * 3;   // x,  batch 1 base

    float s[12];
#pragma unroll
    for (int k = 0; k < 12; ++k) s[k] = 0.f;

    for (int t = threadIdx.x; t < NVERT / 4; t += 256) {
        float4 lv = Lrow[t];
        float  l[4] = {lv.x, lv.y, lv.z, lv.w};
        int    j0   = t * 4;
#pragma unroll
        for (int c = 0; c < 4; ++c) {
            if (l[c] != 0.f) {
                int   j = j0 + c;
                float w = l[c];  // == 1.0f in this dataset; multiply anyway
                const float* p0 = dx  + j * 3;
                const float* p1 = dx1 + j * 3;
                const float* q0 = x   + j * 3;
                const float* q1 = x1  + j * 3;
                s[0] += w * p0[0]; s[1]  += w * p0[1]; s[2]  += w * p0[2];
                s[3] += w * p1[0]; s[4]  += w * p1[1]; s[5]  += w * p1[2];
                s[6] += w * q0[0]; s[7]  += w * q0[1]; s[8]  += w * q0[2];
                s[9] += w * q1[0]; s[10] += w * q1[1]; s[11] += w * q1[2];
                unsigned pos = atomicAdd(&s_cnt, 1u);  // shared atomic: cheap
                if (pos < ROW_CAP)
                    s_list[pos] = ((unsigned)i << 12) | (unsigned)j;
            }
        }
    }

    // ---- reduce the 12 partial sums across the block ----
#pragma unroll
    for (int k = 0; k < 12; ++k)
#pragma unroll
        for (int off = 16; off > 0; off >>= 1)
            s[k] += __shfl_down_sync(0xffffffffu, s[k], off);

    int wid = threadIdx.x >> 5;
    int lid = threadIdx.x & 31;
    if (lid == 0) {
#pragma unroll
        for (int k = 0; k < 12; ++k) s_red[wid][k] = s[k];
    }
    __syncthreads();

    if (threadIdx.x < 12) {
        float v = 0.f;
#pragma unroll
        for (int w = 0; w < 8; ++w) v += s_red[w][threadIdx.x];
        int k = threadIdx.x;
        int b = (k % 6) / 3;
        int d = k % 3;
        if (k < 6) g_dxsub[b * NVERT * 3 + i * 3 + d] = v;
        else       g_xsub [b * NVERT * 3 + i * 3 + d] = v;
    }

    // ---- flush this row's edges: one global atomic per row ----
    if (threadIdx.x == 0) {
        unsigned n = min(s_cnt, (unsigned)ROW_CAP);
        s_base = atomicAdd(&g_num_edges, n);
        s_cnt  = n;
    }
    __syncthreads();
    for (unsigned k = threadIdx.x; k < s_cnt; k += 256)
        g_edges[s_base + k] = s_list[k];
}

// -------- kernel 2: per-edge loss over the compressed edge list -------------
__global__ __launch_bounds__(256) void edge_kernel(
    const float* __restrict__ dx,
    const float* __restrict__ x)
{
    const unsigned n = g_num_edges;
    float a0 = 0.f, a1 = 0.f;

    for (unsigned e = blockIdx.x * 256u + threadIdx.x; e < n;
         e += gridDim.x * 256u) {
        unsigned p = g_edges[e];
        int i = (int)(p >> 12);
        int j = (int)(p & 4095u);

        // batch 0
        {
            float t0 = g_dxsub[j * 3 + 0] - dx[i * 3 + 0];
            float t1 = g_dxsub[j * 3 + 1] - dx[i * 3 + 1];
            float t2 = g_dxsub[j * 3 + 2] - dx[i * 3 + 2];
            float u0 = g_xsub [j * 3 + 0] - x [i * 3 + 0];
            float u1 = g_xsub [j * 3 + 1] - x [i * 3 + 1];
            float u2 = g_xsub [j * 3 + 2] - x [i * 3 + 2];
            float ddx = t0 * t0 + t1 * t1 + t2 * t2;
            float dX  = u0 * u0 + u1 * u1 + u2 * u2;
            a0 += fabsf(dX - ddx);
        }
        // batch 1
        {
            const int o = NVERT * 3;
            float t0 = g_dxsub[o + j * 3 + 0] - dx[o + i * 3 + 0];
            float t1 = g_dxsub[o + j * 3 + 1] - dx[o + i * 3 + 1];
            float t2 = g_dxsub[o + j * 3 + 2] - dx[o + i * 3 + 2];
            float u0 = g_xsub [o + j * 3 + 0] - x [o + i * 3 + 0];
            float u1 = g_xsub [o + j * 3 + 1] - x [o + i * 3 + 1];
            float u2 = g_xsub [o + j * 3 + 2] - x [o + i * 3 + 2];
            float ddx = t0 * t0 + t1 * t1 + t2 * t2;
            float dX  = u0 * u0 + u1 * u1 + u2 * u2;
            a1 += fabsf(dX - ddx);
        }
    }

    // block reduce (a0, a1) then one atomic per block
#pragma unroll
    for (int off = 16; off > 0; off >>= 1) {
        a0 += __shfl_down_sync(0xffffffffu, a0, off);
        a1 += __shfl_down_sync(0xffffffffu, a1, off);
    }
    __shared__ float sa[8][2];
    int wid = threadIdx.x >> 5;
    int lid = threadIdx.x & 31;
    if (lid == 0) { sa[wid][0] = a0; sa[wid][1] = a1; }
    __syncthreads();
    if (threadIdx.x == 0) {
        float t0 = 0.f, t1 = 0.f;
#pragma unroll
        for (int w = 0; w < 8; ++w) { t0 += sa[w][0]; t1 += sa[w][1]; }
        atomicAdd(&g_acc[0], t0);
        atomicAdd(&g_acc[1], t1);
    }
}

// -------- kernel 3: finalize -------------------------------------------------
__global__ void finalize_kernel(float* __restrict__ out) {
    if (threadIdx.x < NBATCH) {
        float n = (float)g_num_edges;
        out[threadIdx.x] = g_acc[threadIdx.x] / n;
    }
}

// -------- launch -------------------------------------------------------------
extern "C" void kernel_launch(void* const* d_in, const int* in_sizes, int n_in,
                              void* d_out, int out_size) {
    // Inputs per metadata order: dx [B,NV,3], x [B,NV,3], laplacian [NV,NV].
    // Identify laplacian by element count; keep dx/x in encounter order
    // (the loss is symmetric in dx<->x anyway).
    const float* lap = nullptr;
    const float* vecs[2] = {nullptr, nullptr};
    int vn = 0;
    for (int k = 0; k < n_in; ++k) {
        if (in_sizes[k] == NVERT * NVERT)
            lap = (const float*)d_in[k];
        else if (vn < 2)
            vecs[vn++] = (const float*)d_in[k];
    }
    if (!lap && n_in >= 3) lap = (const float*)d_in[2];  // defensive fallback
    const float* dx = vecs[0] ? vecs[0] : (const float*)d_in[0];
    const float* x  = vecs[1] ? vecs[1] : (const float*)d_in[1];
    float* out = (float*)d_out;

    init_kernel<<<1, 32>>>();
    matvec_collect_kernel<<<NVERT, 256>>>(lap, dx, x);
    edge_kernel<<<256, 256>>>(dx, x);
    finalize_kernel<<<1, 32>>>(out);
}

// round 3
// speedup vs baseline: 1.0021x; 1.0021x over previous
#include <cuda_runtime.h>
#include <cuda_bf16.h>

#define NVERT 4096
#define NBATCH 2
#define ROW_STRIDE 64          // per-row edge slot stride (max degree << 64)
#define LOG2_STRIDE 6
#define NB_EDGE 256            // edge kernel blocks (must equal its blockDim)

// -------- device scratch (all replay-idempotent: overwritten or self-wrapping)
__device__ float        g_dxsub[NBATCH * NVERT * 3];
__device__ float        g_xsub [NBATCH * NVERT * 3];
__device__ unsigned int g_rowcnt[NVERT];
__device__ unsigned int g_edges[NVERT * ROW_STRIDE];
__device__ float        g_pa0 [NB_EDGE];
__device__ float        g_pa1 [NB_EDGE];
__device__ unsigned int g_pcnt[NB_EDGE];
__device__ unsigned int g_done;   // atomicInc wraps to 0 after last block

// ---------------------------------------------------------------------------
// Kernel 1: fused dense matvec + edge collection.
// One block per row i. Streams the 16KB row exactly once; each thread issues
// its 4 float4 loads up front (MLP=4). Nonzero columns feed 12 FMA
// accumulators (dx/x × B × xyz) and are recorded into fixed-stride slots.
// ---------------------------------------------------------------------------
__global__ __launch_bounds__(256) void matvec_collect_kernel(
    const float* __restrict__ L,
    const float* __restrict__ dx,
    const float* __restrict__ x)
{
    __shared__ unsigned int s_cnt;
    __shared__ float        s_red[8][12];

    if (threadIdx.x == 0) s_cnt = 0u;
    __syncthreads();

    const int i = blockIdx.x;
    const float4* __restrict__ Lrow =
        reinterpret_cast<const float4*>(L + (size_t)i * NVERT);

    const float* __restrict__ dx1 = dx + NVERT * 3;
    const float* __restrict__ x1  = x  + NVERT * 3;

    // 4 front-batched coalesced 16B loads per thread (covers the whole row)
    float4 lv[4];
#pragma unroll
    for (int u = 0; u < 4; ++u)
        lv[u] = Lrow[threadIdx.x + u * 256];

    float s[12];
#pragma unroll
    for (int k = 0; k < 12; ++k) s[k] = 0.f;

#pragma unroll
    for (int u = 0; u < 4; ++u) {
        float l[4] = {lv[u].x, lv[u].y, lv[u].z, lv[u].w};
        int   j0   = (threadIdx.x + u * 256) * 4;
#pragma unroll
        for (int c = 0; c < 4; ++c) {
            if (l[c] != 0.f) {
                int   j = j0 + c;
                float w = l[c];           // == 1.0f here; multiply for exactness
                const float* p0 = dx  + j * 3;
                const float* p1 = dx1 + j * 3;
                const float* q0 = x   + j * 3;
                const float* q1 = x1  + j * 3;
                s[0] += w * p0[0]; s[1]  += w * p0[1]; s[2]  += w * p0[2];
                s[3] += w * p1[0]; s[4]  += w * p1[1]; s[5]  += w * p1[2];
                s[6] += w * q0[0]; s[7]  += w * q0[1]; s[8]  += w * q0[2];
                s[9] += w * q1[0]; s[10] += w * q1[1]; s[11] += w * q1[2];
                unsigned pos = atomicAdd(&s_cnt, 1u);
                if (pos < ROW_STRIDE)
                    g_edges[((unsigned)i << LOG2_STRIDE) + pos] = (unsigned)j;
            }
        }
    }

    // ---- block-reduce the 12 partial sums ----
#pragma unroll
    for (int k = 0; k < 12; ++k)
#pragma unroll
        for (int off = 16; off > 0; off >>= 1)
            s[k] += __shfl_down_sync(0xffffffffu, s[k], off);

    int wid = threadIdx.x >> 5;
    int lid = threadIdx.x & 31;
    if (lid == 0) {
#pragma unroll
        for (int k = 0; k < 12; ++k) s_red[wid][k] = s[k];
    }
    __syncthreads();

    if (threadIdx.x < 12) {
        float v = 0.f;
#pragma unroll
        for (int w = 0; w < 8; ++w) v += s_red[w][threadIdx.x];
        int k = threadIdx.x;
        int b = (k % 6) / 3;
        int d = k % 3;
        if (k < 6) g_dxsub[b * NVERT * 3 + i * 3 + d] = v;
        else       g_xsub [b * NVERT * 3 + i * 3 + d] = v;
    }

    if (threadIdx.x == 0)
        g_rowcnt[i] = min(s_cnt, (unsigned)ROW_STRIDE);   // plain overwrite
}

// ---------------------------------------------------------------------------
// Kernel 2: per-edge loss over the slot array + in-kernel finalize.
// Per-block partials are OVERWRITTEN (no reset needed); the last block
// (detected via self-wrapping atomicInc) reduces them and writes the output.
// ---------------------------------------------------------------------------
__global__ __launch_bounds__(256) void edge_finalize_kernel(
    const float* __restrict__ dx,
    const float* __restrict__ x,
    float* __restrict__ out)
{
    const int tid = threadIdx.x;
    float a0 = 0.f, a1 = 0.f;
    unsigned cnt = 0u;

    const int total = NVERT * ROW_STRIDE;
    for (int sidx = blockIdx.x * 256 + tid; sidx < total;
         sidx += NB_EDGE * 256) {
        int row = sidx >> LOG2_STRIDE;
        int pos = sidx & (ROW_STRIDE - 1);
        if ((unsigned)pos < g_rowcnt[row]) {
            int i = row;
            int j = (int)g_edges[sidx];
            cnt++;
            // batch 0
            {
                float t0 = g_dxsub[j * 3 + 0] - dx[i * 3 + 0];
                float t1 = g_dxsub[j * 3 + 1] - dx[i * 3 + 1];
                float t2 = g_dxsub[j * 3 + 2] - dx[i * 3 + 2];
                float u0 = g_xsub [j * 3 + 0] - x [i * 3 + 0];
                float u1 = g_xsub [j * 3 + 1] - x [i * 3 + 1];
                float u2 = g_xsub [j * 3 + 2] - x [i * 3 + 2];
                a0 += fabsf((u0*u0 + u1*u1 + u2*u2) - (t0*t0 + t1*t1 + t2*t2));
            }
            // batch 1
            {
                const int o = NVERT * 3;
                float t0 = g_dxsub[o + j * 3 + 0] - dx[o + i * 3 + 0];
                float t1 = g_dxsub[o + j * 3 + 1] - dx[o + i * 3 + 1];
                float t2 = g_dxsub[o + j * 3 + 2] - dx[o + i * 3 + 2];
                float u0 = g_xsub [o + j * 3 + 0] - x [o + i * 3 + 0];
                float u1 = g_xsub [o + j * 3 + 1] - x [o + i * 3 + 1];
                float u2 = g_xsub [o + j * 3 + 2] - x [o + i * 3 + 2];
                a1 += fabsf((u0*u0 + u1*u1 + u2*u2) - (t0*t0 + t1*t1 + t2*t2));
            }
        }
    }

    // ---- block reduce (a0, a1, cnt) ----
    float fc = (float)cnt;   // n_edges <= 49152: exact in fp32
#pragma unroll
    for (int off = 16; off > 0; off >>= 1) {
        a0 += __shfl_down_sync(0xffffffffu, a0, off);
        a1 += __shfl_down_sync(0xffffffffu, a1, off);
        fc += __shfl_down_sync(0xffffffffu, fc, off);
    }
    __shared__ float sa[8][3];
    int wid = tid >> 5;
    int lid = tid & 31;
    if (lid == 0) { sa[wid][0] = a0; sa[wid][1] = a1; sa[wid][2] = fc; }
    __syncthreads();
    if (tid == 0) {
        float t0 = 0.f, t1 = 0.f, tc = 0.f;
#pragma unroll
        for (int w = 0; w < 8; ++w) {
            t0 += sa[w][0]; t1 += sa[w][1]; tc += sa[w][2];
        }
        g_pa0 [blockIdx.x] = t0;           // overwrite, no reset needed
        g_pa1 [blockIdx.x] = t1;
        g_pcnt[blockIdx.x] = (unsigned)tc;
    }

    // ---- last-block finalize (g_done wraps to 0 automatically) ----
    __shared__ bool s_last;
    __threadfence();
    if (tid == 0)
        s_last = (atomicInc(&g_done, NB_EDGE - 1) == NB_EDGE - 1);
    __syncthreads();

    if (s_last) {
        float p0 = g_pa0[tid];
        float p1 = g_pa1[tid];
        float pc = (float)g_pcnt[tid];
#pragma unroll
        for (int off = 16; off > 0; off >>= 1) {
            p0 += __shfl_down_sync(0xffffffffu, p0, off);
            p1 += __shfl_down_sync(0xffffffffu, p1, off);
            pc += __shfl_down_sync(0xffffffffu, pc, off);
        }
        if (lid == 0) { sa[wid][0] = p0; sa[wid][1] = p1; sa[wid][2] = pc; }
        __syncthreads();
        if (tid == 0) {
            float t0 = 0.f, t1 = 0.f, n = 0.f;
#pragma unroll
            for (int w = 0; w < 8; ++w) {
                t0 += sa[w][0]; t1 += sa[w][1]; n += sa[w][2];
            }
            out[0] = t0 / n;
            out[1] = t1 / n;
        }
    }
}

// -------- launch -------------------------------------------------------------
extern "C" void kernel_launch(void* const* d_in, const int* in_sizes, int n_in,
                              void* d_out, int out_size) {
    const float* lap = nullptr;
    const float* vecs[2] = {nullptr, nullptr};
    int vn = 0;
    for (int k = 0; k < n_in; ++k) {
        if (in_sizes[k] == NVERT * NVERT)
            lap = (const float*)d_in[k];
        else if (vn < 2)
            vecs[vn++] = (const float*)d_in[k];
    }
    if (!lap && n_in >= 3) lap = (const float*)d_in[2];
    const float* dx = vecs[0] ? vecs[0] : (const float*)d_in[0];
    const float* x  = vecs[1] ? vecs[1] : (const float*)d_in[1];
    float* out = (float*)d_out;

    matvec_collect_kernel<<<NVERT, 256>>>(lap, dx, x);
    edge_finalize_kernel<<<NB_EDGE, 256>>>(dx, x, out);
}